// round 12
// baseline (speedup 1.0000x reference)
#include <cuda_runtime.h>
#include <cstdint>

// ---------------------------------------------------------------------------
// s[b,c] = sum_{i,u} W[i,c,u] * x[b,u,i]; out = squash(s)
// GEMM: D[M=1024 c][N=32 b] = A[c,k] B[k,b], k = i*16+u, K = 32768
// mma.sync.m16n8k8 tf32 + cp.async 5-stage pipeline, 2 CTAs/SM.
// (L2 cache-hint PTX traps on this target — reverted to plain cp.async.)
// ---------------------------------------------------------------------------

#define NB      32
#define NCOL    1024
#define USIZE   64
#define NUNITS  16
#define KS      32        // K-splits (grid.y): 64 i's per CTA
#define CBLK    8         // column blocks of 128 (grid.x)
#define STG     32        // K-stages per CTA; stage = 2 i's = 32 k
#define NS      5         // pipeline depth (smem buffers)

// per-stage smem: A raw fp32 16KB | B frag-ready tf32 4KB
#define BUF_BYTES  20480
#define SM_B_OFF   16384
#define SMEM_TOTAL (NS * BUF_BYTES)     // 100 KB -> 2 CTAs/SM

// Scratch (static device globals; no runtime allocation)
__device__ float g_Bfrag[2048 * 512];        // 4 MB: [i][j], j=np*128+s*64+2l+e
__device__ float g_partial[KS * NB * NCOL];  // 4 MB: [ks][b][c]

__device__ __forceinline__ uint32_t f2tf32(float v) {
    uint32_t r;
    asm("cvt.rna.tf32.f32 %0, %1;" : "=r"(r) : "f"(v));
    return r;
}
__device__ __forceinline__ uint32_t smem_u32(const void* p) {
    uint32_t a;
    asm("{ .reg .u64 t; cvta.to.shared.u64 t, %1; cvt.u32.u64 %0, t; }"
        : "=r"(a) : "l"(p));
    return a;
}
__device__ __forceinline__ void cpa16(uint32_t dst, const void* src) {
    asm volatile("cp.async.cg.shared.global [%0], [%1], 16;"
                 :: "r"(dst), "l"(src));
}
#define CP_COMMIT() asm volatile("cp.async.commit_group;" ::: "memory")
#define CP_WAIT(n)  asm volatile("cp.async.wait_group %0;" :: "n"(n) : "memory")

__device__ __forceinline__ void mma_tf32(float4& d,
                                         uint32_t a0, uint32_t a1,
                                         uint32_t a2, uint32_t a3,
                                         uint32_t b0, uint32_t b1) {
    asm volatile(
        "mma.sync.aligned.m16n8k8.row.col.f32.tf32.tf32.f32 "
        "{%0,%1,%2,%3}, {%4,%5,%6,%7}, {%8,%9}, {%0,%1,%2,%3};"
        : "+f"(d.x), "+f"(d.y), "+f"(d.z), "+f"(d.w)
        : "r"(a0), "r"(a1), "r"(a2), "r"(a3), "r"(b0), "r"(b1));
}

// ---------------------------------------------------------------------------
// Prep: x (B,U,IC) -> g_Bfrag[i][j] = tf32(x[b][u][i])
//   j = np*128 + 64 s + jloc;  jloc = 8g + 2t + e;  b = 8 np + g;
//   u = 4 t + 2 s + e.  KEY: jloc == smem row index r, so with tile
//   t[iloc][r] the write side is LDS.128 of 4 consecutive r + 4 cvt + STG.128.
// Block = (i-tile of 32) x (np, s); grid 512. float4 on both gmem sides.
// ---------------------------------------------------------------------------
#define PTI 32
__global__ void __launch_bounds__(256) k_prep(const float* __restrict__ x) {
    __shared__ float t[PTI][68];            // t[iloc][r], r = jloc = 0..63
    const int bid = blockIdx.x;
    const int s   = bid & 1;
    const int np  = (bid >> 1) & 3;
    const int i0  = (bid >> 3) * PTI;
    const int tid = threadIdx.x;

    // read: 64 (b,u)-rows x 8 float4 (32 i's each)
#pragma unroll
    for (int it = 0; it < 2; ++it) {
        const int idx = it * 256 + tid;       // 0..511
        const int if4 = idx & 7, r = idx >> 3;
        const int g = r >> 3, q = r & 7;
        const int u = 4 * (q >> 1) + 2 * s + (q & 1);
        const float4 v = *(const float4*)
            (x + (size_t)(8 * np + g) * 32768 + (size_t)u * 2048 + i0 + 4 * if4);
        t[4 * if4 + 0][r] = v.x;
        t[4 * if4 + 1][r] = v.y;
        t[4 * if4 + 2][r] = v.z;
        t[4 * if4 + 3][r] = v.w;
    }
    __syncthreads();

    // write: 32 i's x 16 float4 (64 contiguous j's)
    float* const dstbase = g_Bfrag + np * 128 + s * 64;
#pragma unroll
    for (int it = 0; it < 2; ++it) {
        const int idx = it * 256 + tid;
        const int jf4 = idx & 15, iloc = idx >> 4;
        const float4 v = *(const float4*)&t[iloc][4 * jf4];
        uint4 c;
        c.x = f2tf32(v.x); c.y = f2tf32(v.y);
        c.z = f2tf32(v.z); c.w = f2tf32(v.w);
        *(uint4*)(dstbase + (size_t)(i0 + iloc) * 512 + 4 * jf4) = c;
    }
}

// ---------------------------------------------------------------------------
// Main GEMM. grid (CBLK, KS), 256 thr = 8 warps; warp wr owns m-rows
// cb*128 + wr*16 .. +16. cp.async 5-stage ring; K = 1024 per CTA. 2 CTAs/SM.
// Next stage issued BEFORE compute so loads fly under the MMA work.
// ---------------------------------------------------------------------------
__global__ void __launch_bounds__(256, 2) k_main(const float* __restrict__ W) {
    extern __shared__ char sm[];
    const int tid = threadIdx.x;
    const int wr = tid >> 5, l = tid & 31;
    const int g = l >> 2, t4 = l & 3;
    const int cb = blockIdx.x, ks = blockIdx.y;
    const int i00 = ks * 64;

    // issue stage st into ring buffer st%NS
    auto issue = [&](int st) {
        const int ib = i00 + st * 2;
        const uint32_t sa = smem_u32(sm + (st % NS) * BUF_BYTES);
#pragma unroll
        for (int r = 0; r < 4; ++r) {
            const int q = tid + 256 * r;           // 16B chunk id, 0..1023
            const int ii = q >> 9, qi = q & 511;
            cpa16(sa + q * 16,
                  W + (size_t)(ib + ii) * 16384 + cb * 2048 + qi * 4);
        }
        cpa16(sa + SM_B_OFF + tid * 16, g_Bfrag + (size_t)ib * 512 + tid * 4);
    };

#pragma unroll
    for (int st = 0; st < NS - 1; ++st) { issue(st); CP_COMMIT(); }

    float4 acc[4];
#pragma unroll
    for (int np = 0; np < 4; ++np) acc[np] = make_float4(0.f, 0.f, 0.f, 0.f);

    const int arow0 = (wr * 16 + g) * 4 + t4;        // 16B chunk within i-slab
    const int arow1 = (wr * 16 + 8 + g) * 4 + t4;

#pragma unroll 1
    for (int st = 0; st < STG; ++st) {
        CP_WAIT(NS - 2);
        __syncthreads();

        // issue stage st+NS-1 FIRST (barrier above proves buffer st-1 consumed)
        if (st + NS - 1 < STG) issue(st + NS - 1);
        CP_COMMIT();   // always commit to keep group accounting aligned

        char* const buf = sm + (st % NS) * BUF_BYTES;
#pragma unroll
        for (int ii = 0; ii < 2; ++ii) {
            uint4 r0 = *(const uint4*)(buf + (ii * 512 + arow0) * 16);
            uint4 r1 = *(const uint4*)(buf + (ii * 512 + arow1) * 16);
            uint32_t a[8];
            a[0] = f2tf32(__uint_as_float(r0.x));
            a[1] = f2tf32(__uint_as_float(r1.x));
            a[2] = f2tf32(__uint_as_float(r0.y));
            a[3] = f2tf32(__uint_as_float(r1.y));
            a[4] = f2tf32(__uint_as_float(r0.z));
            a[5] = f2tf32(__uint_as_float(r1.z));
            a[6] = f2tf32(__uint_as_float(r0.w));
            a[7] = f2tf32(__uint_as_float(r1.w));
#pragma unroll
            for (int s = 0; s < 2; ++s) {
                const uint32_t a0 = a[s * 4 + 0], a1 = a[s * 4 + 1];
                const uint32_t a2 = a[s * 4 + 2], a3 = a[s * 4 + 3];
#pragma unroll
                for (int np = 0; np < 4; ++np) {
                    float2 bb = *(const float2*)(buf + SM_B_OFF + ii * 2048 +
                                                 ((np * 2 + s) * 64 + l * 2) * 4);
                    mma_tf32(acc[np], a0, a1, a2, a3,
                             __float_as_uint(bb.x), __float_as_uint(bb.y));
                }
            }
        }
    }

    // epilogue: rows g/g+8 of m-tile, cols 2t4/2t4+1 of each n-tile
    const int c0 = cb * 128 + wr * 16 + g;
#pragma unroll
    for (int np = 0; np < 4; ++np) {
        const int b0 = np * 8 + 2 * t4;
        g_partial[((size_t)ks * 32 + b0)     * NCOL + c0]     = acc[np].x;
        g_partial[((size_t)ks * 32 + b0 + 1) * NCOL + c0]     = acc[np].y;
        g_partial[((size_t)ks * 32 + b0)     * NCOL + c0 + 8] = acc[np].z;
        g_partial[((size_t)ks * 32 + b0 + 1) * NCOL + c0 + 8] = acc[np].w;
    }
}

// ---------------------------------------------------------------------------
// Reduce K-splits + squash (fused). grid (32 b, 4 k-chunks), 256 threads.
// ---------------------------------------------------------------------------
__global__ void __launch_bounds__(256) k_squash(float* __restrict__ out) {
    const int b = blockIdx.x, kc = blockIdx.y;
    const int tid = threadIdx.x;
    const int j = tid >> 4, k16 = tid & 15;
    const int k = kc * 16 + k16;
    const int c = j * USIZE + k;

    float s = 0.f;
#pragma unroll
    for (int ks = 0; ks < KS; ++ks)
        s += g_partial[((size_t)ks * 32 + b) * NCOL + c];

    __shared__ float sq[NUNITS][16];
    __shared__ float mag[16];
    sq[j][k16] = s * s;
    __syncthreads();
    if (tid < 16) {
        float m = 0.f;
#pragma unroll
        for (int jj = 0; jj < NUNITS; ++jj) m += sq[jj][tid];
        mag[tid] = m;
    }
    __syncthreads();
    const float m = mag[k16];
    out[b * NCOL + c] = s * m / ((1.0f + m) * sqrtf(m));
}

// ---------------------------------------------------------------------------
extern "C" void kernel_launch(void* const* d_in, const int* in_sizes, int n_in,
                              void* d_out, int out_size) {
    const float* x = (const float*)d_in[0];
    const float* W = (const float*)d_in[1];
    if (n_in >= 2 && in_sizes[0] > in_sizes[1]) {
        W = (const float*)d_in[0];
        x = (const float*)d_in[1];
    }
    float* out = (float*)d_out;

    static bool attr_set = false;
    if (!attr_set) {
        cudaFuncSetAttribute(k_main, cudaFuncAttributeMaxDynamicSharedMemorySize,
                             SMEM_TOTAL);
        attr_set = true;
    }

    k_prep<<<512, 256>>>(x);
    dim3 gm(CBLK, KS);
    k_main<<<gm, 256, SMEM_TOTAL>>>(W);
    dim3 gs(NB, 4);
    k_squash<<<gs, 256>>>(out);
}

// round 14
// speedup vs baseline: 1.0036x; 1.0036x over previous
#include <cuda_runtime.h>
#include <cstdint>

// ---------------------------------------------------------------------------
// s[b,c] = sum_{i,u} W[i,c,u] * x[b,u,i]; out = squash(s)
// GEMM: D[M=1024 c][N=32 b] = A[c,k] B[k,b], k = i*16+u, K = 32768
// mma.sync.m16n8k8 tf32 + cp.async 5-stage ring; grid 8x37 = 296 = 2x148 SMs.
// B scratch layout is a PLAIN transpose B[i][b][u] (fragment-exact).
// ---------------------------------------------------------------------------

#define NB      32
#define NCOL    1024
#define USIZE   64
#define NUNITS  16
#define KS      37        // K-splits (grid.y): 27 or 28 stages (2 i's each)
#define CBLK    8         // column blocks of 128 (grid.x)
#define NS      5         // pipeline depth (smem buffers)

// per-stage smem: A raw fp32 16KB | B tf32 4KB
#define BUF_BYTES  20480
#define SM_B_OFF   16384
#define SMEM_TOTAL (NS * BUF_BYTES)     // 100 KB -> 2 CTAs/SM

// Scratch (static device globals; no runtime allocation)
__device__ float g_Bfrag[2048 * 512];        // 4 MB: [i][b*16+u] = tf32(x[b][u][i])
__device__ float g_partial[KS * NB * NCOL];  // ~4.85 MB: [ks][b][c]

__device__ __forceinline__ uint32_t f2tf32(float v) {
    uint32_t r;
    asm("cvt.rna.tf32.f32 %0, %1;" : "=r"(r) : "f"(v));
    return r;
}
__device__ __forceinline__ uint32_t smem_u32(const void* p) {
    uint32_t a;
    asm("{ .reg .u64 t; cvta.to.shared.u64 t, %1; cvt.u32.u64 %0, t; }"
        : "=r"(a) : "l"(p));
    return a;
}
__device__ __forceinline__ void cpa16(uint32_t dst, const void* src) {
    asm volatile("cp.async.cg.shared.global [%0], [%1], 16;"
                 :: "r"(dst), "l"(src));
}
#define CP_COMMIT() asm volatile("cp.async.commit_group;" ::: "memory")
#define CP_WAIT(n)  asm volatile("cp.async.wait_group %0;" :: "n"(n) : "memory")

__device__ __forceinline__ void mma_tf32(float4& d,
                                         uint32_t a0, uint32_t a1,
                                         uint32_t a2, uint32_t a3,
                                         uint32_t b0, uint32_t b1) {
    asm volatile(
        "mma.sync.aligned.m16n8k8.row.col.f32.tf32.tf32.f32 "
        "{%0,%1,%2,%3}, {%4,%5,%6,%7}, {%8,%9}, {%0,%1,%2,%3};"
        : "+f"(d.x), "+f"(d.y), "+f"(d.z), "+f"(d.w)
        : "r"(a0), "r"(a1), "r"(a2), "r"(a3), "r"(b0), "r"(b1));
}

// ---------------------------------------------------------------------------
// Prep: plain tiled transpose  x[b][u][i] -> g_Bfrag[i][b*16+u] (tf32).
// Block = (i-tile 16) x (b-group of 8); grid 512, 256 thr, ~30 instrs/thread.
// ---------------------------------------------------------------------------
__global__ void __launch_bounds__(256) k_prep(const float* __restrict__ x) {
    __shared__ float t[128 * 17];           // t[r][iloc], r = bb*16+u, pad 17
    const int bid = blockIdx.x;
    const int bg  = bid & 3;                // b-group (8 b's)
    const int i0  = (bid >> 2) * 16;
    const int tid = threadIdx.x;

    // read: 128 (bb,u)-rows x 4 float4 (16 i's)
#pragma unroll
    for (int it = 0; it < 2; ++it) {
        const int idx = it * 256 + tid;     // 0..511
        const int c4 = idx & 3, r = idx >> 2;
        const int bb = r >> 4, u = r & 15;
        const float4 v = *(const float4*)
            (x + (size_t)(bg * 8 + bb) * 32768 + (size_t)u * 2048 + i0 + 4 * c4);
        float* row = t + r * 17 + 4 * c4;
        row[0] = v.x; row[1] = v.y; row[2] = v.z; row[3] = v.w;
    }
    __syncthreads();

    // write: per i, 32 float4 = 128 contiguous floats (this b-group's chunk)
#pragma unroll
    for (int it = 0; it < 2; ++it) {
        const int idx = it * 256 + tid;
        const int f = idx & 31, iloc = idx >> 5;   // f: float4 id within chunk
        const float* col = t + (4 * f) * 17 + iloc;
        uint4 c;
        c.x = f2tf32(col[0]);
        c.y = f2tf32(col[17]);
        c.z = f2tf32(col[34]);
        c.w = f2tf32(col[51]);
        *(uint4*)(g_Bfrag + (size_t)(i0 + iloc) * 512 + bg * 128 + 4 * f) = c;
    }
}

// ---------------------------------------------------------------------------
// Main GEMM. grid (CBLK, KS=37) = 296 CTAs = 2/SM exactly. 256 thr = 8 warps;
// warp wr owns m-rows cb*128 + wr*16 .. +16. Stage = 2 i's; CTA does its
// [start,end) stage range (27 or 28). B loads are conflict-free LDS.128.
// ---------------------------------------------------------------------------
__global__ void __launch_bounds__(256, 2) k_main(const float* __restrict__ W) {
    extern __shared__ char sm[];
    const int tid = threadIdx.x;
    const int wr = tid >> 5, l = tid & 31;
    const int g = l >> 2, t4 = l & 3;
    const int cb = blockIdx.x, ks = blockIdx.y;

    const int start = (ks * 1024) / KS;
    const int nst   = ((ks + 1) * 1024) / KS - start;
    const int i00   = start * 2;

    // issue stage st into ring buffer st%NS
    auto issue = [&](int st) {
        const int ib = i00 + st * 2;
        const uint32_t sa = smem_u32(sm + (st % NS) * BUF_BYTES);
#pragma unroll
        for (int r = 0; r < 4; ++r) {
            const int q = tid + 256 * r;           // 16B chunk id, 0..1023
            const int ii = q >> 9, qi = q & 511;
            cpa16(sa + q * 16,
                  W + (size_t)(ib + ii) * 16384 + cb * 2048 + qi * 4);
        }
        // B: 2 i-slabs = 4KB contiguous in g_Bfrag
        cpa16(sa + SM_B_OFF + tid * 16, g_Bfrag + (size_t)ib * 512 + tid * 4);
    };

#pragma unroll
    for (int st = 0; st < NS - 1; ++st) {
        if (st < nst) issue(st);
        CP_COMMIT();
    }

    float4 acc[4];
#pragma unroll
    for (int np = 0; np < 4; ++np) acc[np] = make_float4(0.f, 0.f, 0.f, 0.f);

    const int arow0 = (wr * 16 + g) * 4 + t4;        // 16B chunk within i-slab
    const int arow1 = (wr * 16 + 8 + g) * 4 + t4;
    const int boff  = (16 * g + 4 * t4) * 4;         // byte offset of B float4

#pragma unroll 1
    for (int st = 0; st < nst; ++st) {
        CP_WAIT(NS - 2);
        __syncthreads();

        // issue stage st+NS-1 FIRST (barrier above proves buffer st-1 consumed)
        if (st + NS - 1 < nst) issue(st + NS - 1);
        CP_COMMIT();   // always commit to keep group accounting aligned

        char* const buf = sm + (st % NS) * BUF_BYTES;
#pragma unroll
        for (int ii = 0; ii < 2; ++ii) {
            uint4 r0 = *(const uint4*)(buf + (ii * 512 + arow0) * 16);
            uint4 r1 = *(const uint4*)(buf + (ii * 512 + arow1) * 16);
            uint32_t a[8];
            a[0] = f2tf32(__uint_as_float(r0.x));
            a[1] = f2tf32(__uint_as_float(r1.x));
            a[2] = f2tf32(__uint_as_float(r0.y));
            a[3] = f2tf32(__uint_as_float(r1.y));
            a[4] = f2tf32(__uint_as_float(r0.z));
            a[5] = f2tf32(__uint_as_float(r1.z));
            a[6] = f2tf32(__uint_as_float(r0.w));
            a[7] = f2tf32(__uint_as_float(r1.w));
#pragma unroll
            for (int np = 0; np < 4; ++np) {
                // B[i=ii][b=8np+g][u=4t4..4t4+3]: s=0 -> (x,y), s=1 -> (z,w)
                float4 bb = *(const float4*)(buf + SM_B_OFF + ii * 2048 +
                                             np * 512 + boff);
                mma_tf32(acc[np], a[0], a[1], a[2], a[3],
                         __float_as_uint(bb.x), __float_as_uint(bb.y));
                mma_tf32(acc[np], a[4], a[5], a[6], a[7],
                         __float_as_uint(bb.z), __float_as_uint(bb.w));
            }
        }
    }

    // epilogue: rows g/g+8 of m-tile, cols 2t4/2t4+1 of each n-tile
    const int c0 = cb * 128 + wr * 16 + g;
#pragma unroll
    for (int np = 0; np < 4; ++np) {
        const int b0 = np * 8 + 2 * t4;
        g_partial[((size_t)ks * 32 + b0)     * NCOL + c0]     = acc[np].x;
        g_partial[((size_t)ks * 32 + b0 + 1) * NCOL + c0]     = acc[np].y;
        g_partial[((size_t)ks * 32 + b0)     * NCOL + c0 + 8] = acc[np].z;
        g_partial[((size_t)ks * 32 + b0 + 1) * NCOL + c0 + 8] = acc[np].w;
    }
}

// ---------------------------------------------------------------------------
// Reduce K-splits + squash (fused). grid (32 b, 4 k-chunks), 256 threads.
// ---------------------------------------------------------------------------
__global__ void __launch_bounds__(256) k_squash(float* __restrict__ out) {
    const int b = blockIdx.x, kc = blockIdx.y;
    const int tid = threadIdx.x;
    const int j = tid >> 4, k16 = tid & 15;
    const int k = kc * 16 + k16;
    const int c = j * USIZE + k;

    float s = 0.f;
#pragma unroll
    for (int ks = 0; ks < KS; ++ks)
        s += g_partial[((size_t)ks * 32 + b) * NCOL + c];

    __shared__ float sq[NUNITS][16];
    __shared__ float mag[16];
    sq[j][k16] = s * s;
    __syncthreads();
    if (tid < 16) {
        float m = 0.f;
#pragma unroll
        for (int jj = 0; jj < NUNITS; ++jj) m += sq[jj][tid];
        mag[tid] = m;
    }
    __syncthreads();
    const float m = mag[k16];
    out[b * NCOL + c] = s * m / ((1.0f + m) * sqrtf(m));
}

// ---------------------------------------------------------------------------
extern "C" void kernel_launch(void* const* d_in, const int* in_sizes, int n_in,
                              void* d_out, int out_size) {
    const float* x = (const float*)d_in[0];
    const float* W = (const float*)d_in[1];
    if (n_in >= 2 && in_sizes[0] > in_sizes[1]) {
        W = (const float*)d_in[0];
        x = (const float*)d_in[1];
    }
    float* out = (float*)d_out;

    static bool attr_set = false;
    if (!attr_set) {
        cudaFuncSetAttribute(k_main, cudaFuncAttributeMaxDynamicSharedMemorySize,
                             SMEM_TOTAL);
        attr_set = true;
    }

    k_prep<<<512, 256>>>(x);
    dim3 gm(CBLK, KS);
    k_main<<<gm, 256, SMEM_TOTAL>>>(W);
    dim3 gs(NB, 4);
    k_squash<<<gs, 256>>>(out);
}

// round 16
// speedup vs baseline: 1.0683x; 1.0644x over previous
#include <cuda_runtime.h>
#include <cstdint>

// ---------------------------------------------------------------------------
// s[b,c] = sum_{i,u} W[i,c,u] * x[b,u,i]; out = squash(s)
// GEMM: D[M=1024 c][N=32 b] = A[c,k] B[k,b], k = i*16+u, K = 32768
// mma.sync.m16n8k8 tf32 + cp.async 5-stage ring; grid 8x37 = 296 = 2x148 SMs.
// K-split partials accumulated via atomicAdd into g_s (no g_partial traffic).
// ---------------------------------------------------------------------------

#define NB      32
#define NCOL    1024
#define USIZE   64
#define NUNITS  16
#define KS      37        // K-splits (grid.y): 27 or 28 stages (2 i's each)
#define CBLK    8         // column blocks of 128 (grid.x)
#define NS      5         // pipeline depth (smem buffers)

// per-stage smem: A raw fp32 16KB | B tf32 4KB
#define BUF_BYTES  20480
#define SM_B_OFF   16384
#define SMEM_TOTAL (NS * BUF_BYTES)     // 100 KB -> 2 CTAs/SM

// Scratch (static device globals; no runtime allocation)
__device__ float g_Bfrag[2048 * 512];   // 4 MB: [i][b*16+u] = tf32(x[b][u][i])
__device__ float g_s[NB * NCOL];        // 128 KB: [b][c], atomically accumulated

__device__ __forceinline__ uint32_t f2tf32(float v) {
    uint32_t r;
    asm("cvt.rna.tf32.f32 %0, %1;" : "=r"(r) : "f"(v));
    return r;
}
__device__ __forceinline__ uint32_t smem_u32(const void* p) {
    uint32_t a;
    asm("{ .reg .u64 t; cvta.to.shared.u64 t, %1; cvt.u32.u64 %0, t; }"
        : "=r"(a) : "l"(p));
    return a;
}
__device__ __forceinline__ void cpa16(uint32_t dst, const void* src) {
    asm volatile("cp.async.cg.shared.global [%0], [%1], 16;"
                 :: "r"(dst), "l"(src));
}
#define CP_COMMIT() asm volatile("cp.async.commit_group;" ::: "memory")
#define CP_WAIT(n)  asm volatile("cp.async.wait_group %0;" :: "n"(n) : "memory")

__device__ __forceinline__ void mma_tf32(float4& d,
                                         uint32_t a0, uint32_t a1,
                                         uint32_t a2, uint32_t a3,
                                         uint32_t b0, uint32_t b1) {
    asm volatile(
        "mma.sync.aligned.m16n8k8.row.col.f32.tf32.tf32.f32 "
        "{%0,%1,%2,%3}, {%4,%5,%6,%7}, {%8,%9}, {%0,%1,%2,%3};"
        : "+f"(d.x), "+f"(d.y), "+f"(d.z), "+f"(d.w)
        : "r"(a0), "r"(a1), "r"(a2), "r"(a3), "r"(b0), "r"(b1));
}

// ---------------------------------------------------------------------------
// Prep: x[b][u][i] -> g_Bfrag[i][b*16+u] (tf32), minimal dependence depth:
// no smem, no sync. Thread o: bu = o&511, i-quad = o>>9.
//   read : LDG.128 of x[bu-row][4iq..4iq+3]   (32 rows/warp, 16B each)
//   write: 4 STG.32; per warp lanes span 32 consecutive bu -> 128B coalesced.
// Also zeroes g_s (first 32768 threads) before k_main's atomics.
// ---------------------------------------------------------------------------
__global__ void __launch_bounds__(256) k_prep(const float* __restrict__ x) {
    const int o = blockIdx.x * 256 + threadIdx.x;       // 0..262143
    const int bu = o & 511;
    const int iq = o >> 9;
    const int b = bu >> 4, u = bu & 15;

    if (o < NB * NCOL) g_s[o] = 0.f;

    const float4 v = *(const float4*)
        (x + (size_t)b * 32768 + (size_t)u * 2048 + 4 * iq);
    float* dst = g_Bfrag + (size_t)(4 * iq) * 512 + bu;
    dst[0]    = __uint_as_float(f2tf32(v.x));
    dst[512]  = __uint_as_float(f2tf32(v.y));
    dst[1024] = __uint_as_float(f2tf32(v.z));
    dst[1536] = __uint_as_float(f2tf32(v.w));
}

// ---------------------------------------------------------------------------
// Main GEMM. grid (CBLK, KS=37) = 296 CTAs = 2/SM exactly. 256 thr = 8 warps;
// warp wr owns m-rows cb*128 + wr*16 .. +16. Stage = 2 i's; CTA does its
// [start,end) stage range (27 or 28). Epilogue: atomicAdd into g_s.
// ---------------------------------------------------------------------------
__global__ void __launch_bounds__(256, 2) k_main(const float* __restrict__ W) {
    extern __shared__ char sm[];
    const int tid = threadIdx.x;
    const int wr = tid >> 5, l = tid & 31;
    const int g = l >> 2, t4 = l & 3;
    const int cb = blockIdx.x, ks = blockIdx.y;

    const int start = (ks * 1024) / KS;
    const int nst   = ((ks + 1) * 1024) / KS - start;
    const int i00   = start * 2;

    // issue stage st into ring buffer st%NS
    auto issue = [&](int st) {
        const int ib = i00 + st * 2;
        const uint32_t sa = smem_u32(sm + (st % NS) * BUF_BYTES);
#pragma unroll
        for (int r = 0; r < 4; ++r) {
            const int q = tid + 256 * r;           // 16B chunk id, 0..1023
            const int ii = q >> 9, qi = q & 511;
            cpa16(sa + q * 16,
                  W + (size_t)(ib + ii) * 16384 + cb * 2048 + qi * 4);
        }
        // B: 2 i-slabs = 4KB contiguous in g_Bfrag
        cpa16(sa + SM_B_OFF + tid * 16, g_Bfrag + (size_t)ib * 512 + tid * 4);
    };

#pragma unroll
    for (int st = 0; st < NS - 1; ++st) {
        if (st < nst) issue(st);
        CP_COMMIT();
    }

    float4 acc[4];
#pragma unroll
    for (int np = 0; np < 4; ++np) acc[np] = make_float4(0.f, 0.f, 0.f, 0.f);

    const int arow0 = (wr * 16 + g) * 4 + t4;        // 16B chunk within i-slab
    const int arow1 = (wr * 16 + 8 + g) * 4 + t4;
    const int boff  = (16 * g + 4 * t4) * 4;         // byte offset of B float4

#pragma unroll 1
    for (int st = 0; st < nst; ++st) {
        CP_WAIT(NS - 2);
        __syncthreads();

        // issue stage st+NS-1 FIRST (barrier above proves buffer st-1 consumed)
        if (st + NS - 1 < nst) issue(st + NS - 1);
        CP_COMMIT();   // always commit to keep group accounting aligned

        char* const buf = sm + (st % NS) * BUF_BYTES;
#pragma unroll
        for (int ii = 0; ii < 2; ++ii) {
            uint4 r0 = *(const uint4*)(buf + (ii * 512 + arow0) * 16);
            uint4 r1 = *(const uint4*)(buf + (ii * 512 + arow1) * 16);
            uint32_t a[8];
            a[0] = f2tf32(__uint_as_float(r0.x));
            a[1] = f2tf32(__uint_as_float(r1.x));
            a[2] = f2tf32(__uint_as_float(r0.y));
            a[3] = f2tf32(__uint_as_float(r1.y));
            a[4] = f2tf32(__uint_as_float(r0.z));
            a[5] = f2tf32(__uint_as_float(r1.z));
            a[6] = f2tf32(__uint_as_float(r0.w));
            a[7] = f2tf32(__uint_as_float(r1.w));
#pragma unroll
            for (int np = 0; np < 4; ++np) {
                // B[i=ii][b=8np+g][u=4t4..4t4+3]: s=0 -> (x,y), s=1 -> (z,w)
                float4 bb = *(const float4*)(buf + SM_B_OFF + ii * 2048 +
                                             np * 512 + boff);
                mma_tf32(acc[np], a[0], a[1], a[2], a[3],
                         __float_as_uint(bb.x), __float_as_uint(bb.y));
                mma_tf32(acc[np], a[4], a[5], a[6], a[7],
                         __float_as_uint(bb.z), __float_as_uint(bb.w));
            }
        }
    }

    // epilogue: accumulate directly into g_s (rows g/g+8, cols 2t4/2t4+1)
    const int c0 = cb * 128 + wr * 16 + g;
#pragma unroll
    for (int np = 0; np < 4; ++np) {
        const int b0 = np * 8 + 2 * t4;
        atomicAdd(&g_s[(b0)     * NCOL + c0],     acc[np].x);
        atomicAdd(&g_s[(b0 + 1) * NCOL + c0],     acc[np].y);
        atomicAdd(&g_s[(b0)     * NCOL + c0 + 8], acc[np].z);
        atomicAdd(&g_s[(b0 + 1) * NCOL + c0 + 8], acc[np].w);
    }
}

// ---------------------------------------------------------------------------
// Squash. grid (32 b, 4 k-chunks), 256 threads; reads 128KB g_s.
// ---------------------------------------------------------------------------
__global__ void __launch_bounds__(256) k_squash(float* __restrict__ out) {
    const int b = blockIdx.x, kc = blockIdx.y;
    const int tid = threadIdx.x;
    const int j = tid >> 4, k16 = tid & 15;
    const int k = kc * 16 + k16;
    const int c = j * USIZE + k;

    const float s = g_s[b * NCOL + c];

    __shared__ float sq[NUNITS][16];
    __shared__ float mag[16];
    sq[j][k16] = s * s;
    __syncthreads();
    if (tid < 16) {
        float m = 0.f;
#pragma unroll
        for (int jj = 0; jj < NUNITS; ++jj) m += sq[jj][tid];
        mag[tid] = m;
    }
    __syncthreads();
    const float m = mag[k16];
    out[b * NCOL + c] = s * m / ((1.0f + m) * sqrtf(m));
}

// ---------------------------------------------------------------------------
extern "C" void kernel_launch(void* const* d_in, const int* in_sizes, int n_in,
                              void* d_out, int out_size) {
    const float* x = (const float*)d_in[0];
    const float* W = (const float*)d_in[1];
    if (n_in >= 2 && in_sizes[0] > in_sizes[1]) {
        W = (const float*)d_in[0];
        x = (const float*)d_in[1];
    }
    float* out = (float*)d_out;

    static bool attr_set = false;
    if (!attr_set) {
        cudaFuncSetAttribute(k_main, cudaFuncAttributeMaxDynamicSharedMemorySize,
                             SMEM_TOTAL);
        attr_set = true;
    }

    k_prep<<<1024, 256>>>(x);
    dim3 gm(CBLK, KS);
    k_main<<<gm, 256, SMEM_TOTAL>>>(W);
    dim3 gs(NB, 4);
    k_squash<<<gs, 256>>>(out);
}